// round 6
// baseline (speedup 1.0000x reference)
#include <cuda_runtime.h>

#define NQ      14
#define DIM     (1 << NQ)           // 16384 amplitudes
#define NL      8
#define NGATES  ((NL + 1) * NQ)     // 126 single-qubit gates
#define THREADS 512
#define PER_T   (DIM / THREADS)     // 32 amplitudes per thread
#define PAIRS_T (DIM / 2 / THREADS) // 16 pairs per thread per gate

// One CTA simulates one (batch, circuit) pair. State lives in dynamic SMEM.
__global__ void __launch_bounds__(THREADS, 1)
pqc_kernel(const float* __restrict__ x,
           const float* __restrict__ qx1, const float* __restrict__ qz1,
           const float* __restrict__ c1,
           const float* __restrict__ qx2, const float* __restrict__ qz2,
           const float* __restrict__ c2,
           float* __restrict__ out, int B)
{
    extern __shared__ float2 st[];           // DIM complex amplitudes
    __shared__ float U[NGATES][8];           // precomputed 2x2 complex gates
    __shared__ float csh[NQ];                // observable coefficients
    __shared__ float amp[NQ][2];             // per-qubit init amplitudes
    __shared__ float wsum[THREADS / 32];

    const int tid  = threadIdx.x;
    const int b    = blockIdx.x;
    const int circ = blockIdx.y;

    const float* qx = circ ? qx2 : qx1;
    const float* qz = circ ? qz2 : qz1;
    const float* cc = circ ? c2  : c1;

    // ---- Precompute all gate matrices (one gate per thread) ----
    // U = [[pm*cx, pm*(-i sx)], [pp*(-i sx), pp*cx]],
    // pm = exp(-i qz/2) = (pr, pii), pp = conj(pm)
    if (tid < NGATES) {
        float ax = 0.5f * qx[tid];
        float az = 0.5f * qz[tid];
        float cxv = cosf(ax), sxv = sinf(ax);
        float pr  = cosf(az), pii = -sinf(az);
        float* u = U[tid];
        u[0] =  pr  * cxv;  u[1] =  pii * cxv;   // U00
        u[2] =  pii * sxv;  u[3] = -pr  * sxv;   // U01
        u[4] = -pii * sxv;  u[5] = -pr  * sxv;   // U10
        u[6] =  pr  * cxv;  u[7] = -pii * cxv;   // U11
    }
    if (tid < NQ) {
        csh[tid] = cc[tid];
        float bit = (x[b * NQ + tid] > 0.0f) ? 1.0f : 0.0f;
        float th = 1.5707963705062866f * bit;    // 0.5f * float32(pi) * bit
        amp[tid][0] = cosf(th);
        amp[tid][1] = sinf(th);
    }
    __syncthreads();

    // ---- Init: exact product state (wire 0 is MSB) ----
    #pragma unroll
    for (int k = 0; k < PER_T; k++) {
        int i = tid + k * THREADS;
        float p = 1.0f;
        #pragma unroll
        for (int w = 0; w < NQ; w++)
            p *= amp[w][(i >> (NQ - 1 - w)) & 1];
        st[i] = make_float2(p, 0.0f);
    }
    __syncthreads();

    // ---- Layers ----
    for (int l = 0; l <= NL; l++) {
        // 14 single-qubit rotations
        for (int w = 0; w < NQ; w++) {
            const float* u = U[l * NQ + w];
            const float u00r = u[0], u00i = u[1], u01r = u[2], u01i = u[3];
            const float u10r = u[4], u10i = u[5], u11r = u[6], u11i = u[7];
            const int pos = NQ - 1 - w;
            const int m   = 1 << pos;
            #pragma unroll
            for (int k = 0; k < PAIRS_T; k++) {
                int p  = tid + k * THREADS;
                int i0 = ((p >> pos) << (pos + 1)) | (p & (m - 1));
                int i1 = i0 + m;
                float2 a0 = st[i0], a1 = st[i1];
                float2 r0, r1;
                r0.x = u00r * a0.x - u00i * a0.y + u01r * a1.x - u01i * a1.y;
                r0.y = u00r * a0.y + u00i * a0.x + u01r * a1.y + u01i * a1.x;
                r1.x = u10r * a0.x - u10i * a0.y + u11r * a1.x - u11i * a1.y;
                r1.y = u10r * a0.y + u10i * a0.x + u11r * a1.y + u11i * a1.x;
                st[i0] = r0;
                st[i1] = r1;
            }
            __syncthreads();
        }
        // CNOT ladder (w = 0..12) == Gray-code permutation: src = j ^ (j>>1)
        if (l < NL) {
            float2 tmp[PER_T];
            #pragma unroll
            for (int k = 0; k < PER_T; k++) {
                int j = tid + k * THREADS;
                tmp[k] = st[j ^ (j >> 1)];
            }
            __syncthreads();
            #pragma unroll
            for (int k = 0; k < PER_T; k++)
                st[tid + k * THREADS] = tmp[k];
            __syncthreads();
        }
    }

    // ---- Expectation: sum |a_i|^2 * g(i), g(i) = sum_w (+/- c_w) ----
    float creg[NQ];
    #pragma unroll
    for (int w = 0; w < NQ; w++) creg[w] = csh[w];

    float local = 0.0f;
    #pragma unroll
    for (int k = 0; k < PER_T; k++) {
        int i = tid + k * THREADS;
        float2 a = st[i];
        float prob = a.x * a.x + a.y * a.y;
        float g = 0.0f;
        #pragma unroll
        for (int w = 0; w < NQ; w++)
            g += ((i >> (NQ - 1 - w)) & 1) ? -creg[w] : creg[w];
        local += prob * g;
    }

    #pragma unroll
    for (int off = 16; off; off >>= 1)
        local += __shfl_down_sync(0xffffffffu, local, off);
    if ((tid & 31) == 0) wsum[tid >> 5] = local;
    __syncthreads();
    if (tid == 0) {
        float tot = 0.0f;
        #pragma unroll
        for (int i = 0; i < THREADS / 32; i++) tot += wsum[i];
        // PLANAR complex output: out[0..B) = real part (f1),
        //                        out[B..2B) = imag part (f2).
        out[circ * B + b] = tot;
    }
}

extern "C" void kernel_launch(void* const* d_in, const int* in_sizes, int n_in,
                              void* d_out, int out_size)
{
    // Input slot dispatch by element count:
    //   x = B*NQ (3584, unique large), q_* = 126 (x4), c_* = 14 (x2).
    const float *x, *qx1, *qz1, *c1, *qx2, *qz2, *c2;

    if (n_in >= 7 && in_sizes[0] > 1000) {
        // dict order: x, q_x1, q_z1, c1, q_x2, q_z2, c2
        x   = (const float*)d_in[0];
        qx1 = (const float*)d_in[1];
        qz1 = (const float*)d_in[2];
        c1  = (const float*)d_in[3];
        qx2 = (const float*)d_in[4];
        qz2 = (const float*)d_in[5];
        c2  = (const float*)d_in[6];
    } else if (n_in >= 7 && in_sizes[0] == NQ && in_sizes[1] == NQ) {
        // alphabetical: c1, c2, q_x1, q_x2, q_z1, q_z2, x
        c1  = (const float*)d_in[0];
        c2  = (const float*)d_in[1];
        qx1 = (const float*)d_in[2];
        qx2 = (const float*)d_in[3];
        qz1 = (const float*)d_in[4];
        qz2 = (const float*)d_in[5];
        x   = (const float*)d_in[6];
    } else {
        // Generic fallback: classify by size, in-class appearance order.
        const float* qs[4] = {0, 0, 0, 0};
        const float* cs[2] = {0, 0};
        const float* xp = 0;
        int nq = 0, nc = 0;
        for (int i = 0; i < n_in; i++) {
            if (in_sizes[i] > 1000)       xp = (const float*)d_in[i];
            else if (in_sizes[i] == NGATES) { if (nq < 4) qs[nq++] = (const float*)d_in[i]; }
            else if (in_sizes[i] == NQ)     { if (nc < 2) cs[nc++] = (const float*)d_in[i]; }
        }
        x = xp; qx1 = qs[0]; qz1 = qs[1]; qx2 = qs[2]; qz2 = qs[3];
        c1 = cs[0]; c2 = cs[1];
    }

    int xsz = 0;
    for (int i = 0; i < n_in; i++) if (in_sizes[i] > xsz) xsz = in_sizes[i];
    const int B = xsz / NQ;  // 256

    cudaFuncSetAttribute(pqc_kernel,
                         cudaFuncAttributeMaxDynamicSharedMemorySize,
                         DIM * sizeof(float2));

    dim3 grid(B, 2);
    pqc_kernel<<<grid, THREADS, DIM * sizeof(float2)>>>(
        x, qx1, qz1, c1, qx2, qz2, c2, (float*)d_out, B);
}

// round 7
// speedup vs baseline: 1.8833x; 1.8833x over previous
#include <cuda_runtime.h>

#define NQ      14
#define DIM     (1 << NQ)          // 16384 amplitudes
#define NL      8
#define NGATES  ((NL + 1) * NQ)    // 126 single-qubit gates
#define THREADS 512
#define RPT     32                 // register amplitudes per thread

// Bank-conflict-avoiding physical index for the shared-memory state array.
// Bijective; identical mapping used by every pass, so correctness only needs
// each pass to agree on phys().
__device__ __forceinline__ int phys(int i) { return i ^ ((i >> 5) & 31); }

// One complex 2x2 butterfly; operand evaluation order matches the
// straightforward scalar expansion (mul + 3 fma per component).
#define BF(A0, A1) do {                                         \
    float2 _r0, _r1;                                            \
    _r0.x = v0*(A0).x - v1*(A0).y + v2*(A1).x - v3*(A1).y;      \
    _r0.y = v0*(A0).y + v1*(A0).x + v2*(A1).y + v3*(A1).x;      \
    _r1.x = v4*(A0).x - v5*(A0).y + v6*(A1).x - v7*(A1).y;      \
    _r1.y = v4*(A0).y + v5*(A0).x + v6*(A1).y + v7*(A1).x;      \
    (A0) = _r0; (A1) = _r1;                                     \
} while (0)

// Apply gate `gidx` as a butterfly on register-index bit `bit` (compile-time
// after unrolling) of the 32-element register block R.
#define APPLY(gidx, bit) do {                                   \
    const float* _u = U[gidx];                                  \
    const float v0=_u[0], v1=_u[1], v2=_u[2], v3=_u[3],         \
                v4=_u[4], v5=_u[5], v6=_u[6], v7=_u[7];         \
    _Pragma("unroll")                                           \
    for (int _k = 0; _k < RPT; _k++)                            \
        if (!(_k & (1 << (bit))))                               \
            BF(R[_k], R[_k | (1 << (bit))]);                    \
} while (0)

// One CTA simulates one (batch, circuit) pair. State lives in dynamic SMEM;
// each layer is processed in 3 register-blocked passes of 5/5/4 gates.
__global__ void __launch_bounds__(THREADS, 1)
pqc_kernel(const float* __restrict__ x,
           const float* __restrict__ qx1, const float* __restrict__ qz1,
           const float* __restrict__ c1,
           const float* __restrict__ qx2, const float* __restrict__ qz2,
           const float* __restrict__ c2,
           float* __restrict__ out, int B)
{
    extern __shared__ float2 st[];           // DIM complex amplitudes (swizzled)
    __shared__ float U[NGATES][8];           // precomputed 2x2 complex gates
    __shared__ float csh[NQ];                // observable coefficients
    __shared__ float amp[NQ][2];             // per-qubit init amplitudes
    __shared__ float wsum[THREADS / 32];

    const int tid  = threadIdx.x;
    const int b    = blockIdx.x;
    const int circ = blockIdx.y;

    const float* qx = circ ? qx2 : qx1;
    const float* qz = circ ? qz2 : qz1;
    const float* cc = circ ? c2  : c1;

    // ---- Precompute gate matrices: U = [[pm*cx, pm*(-i sx)],[pp*(-i sx), pp*cx]]
    if (tid < NGATES) {
        float ax = 0.5f * qx[tid];
        float az = 0.5f * qz[tid];
        float cxv = cosf(ax), sxv = sinf(ax);
        float pr  = cosf(az), pii = -sinf(az);  // pm = (pr, pii), pp = conj(pm)
        float* u = U[tid];
        u[0] =  pr  * cxv;  u[1] =  pii * cxv;  // U00
        u[2] =  pii * sxv;  u[3] = -pr  * sxv;  // U01
        u[4] = -pii * sxv;  u[5] = -pr  * sxv;  // U10
        u[6] =  pr  * cxv;  u[7] = -pii * cxv;  // U11
    }
    if (tid < NQ) {
        csh[tid] = cc[tid];
        float bit = (x[b * NQ + tid] > 0.0f) ? 1.0f : 0.0f;
        float th = 1.5707963705062866f * bit;   // 0.5f * float32(pi) * bit
        amp[tid][0] = cosf(th);
        amp[tid][1] = sinf(th);
    }
    __syncthreads();

    float2 R[RPT];
    float  local = 0.0f;

    for (int l = 0; l <= NL; l++) {
        // ============ Pass A: index bits 0..4  (wires 13..9) ============
        if (l == 0) {
            // init product state directly into registers (reference mult order)
            float ph = 1.0f;
            #pragma unroll
            for (int w = 0; w < 9; w++)
                ph *= amp[w][(tid >> (8 - w)) & 1];   // i bit (13-w) == tid bit (8-w)
            #pragma unroll
            for (int k = 0; k < RPT; k++) {
                float p = ph;
                #pragma unroll
                for (int w = 9; w < NQ; w++)
                    p *= amp[w][(k >> (13 - w)) & 1];
                R[k] = make_float2(p, 0.0f);
            }
        } else {
            // fused CNOT-ladder permutation: dst j <- src j ^ (j>>1)
            #pragma unroll
            for (int k = 0; k < RPT; k++) {
                int j = (tid << 5) | k;
                int s = j ^ (j >> 1);
                R[k] = st[phys(s)];
            }
        }
        #pragma unroll
        for (int p = 0; p < 5; p++)
            APPLY(l * NQ + (13 - p), p);
        if (l > 0) __syncthreads();   // gathered sources must be read by all first
        #pragma unroll
        for (int k = 0; k < RPT; k++)
            st[phys((tid << 5) | k)] = R[k];
        __syncthreads();

        // ============ Pass B: index bits 5..9  (wires 8..4) ============
        {
            const int base = ((tid >> 5) << 10) | (tid & 31);
            #pragma unroll
            for (int k = 0; k < RPT; k++)
                R[k] = st[phys(base | (k << 5))];
            #pragma unroll
            for (int p = 0; p < 5; p++)
                APPLY(l * NQ + (8 - p), p);
            #pragma unroll
            for (int k = 0; k < RPT; k++)
                st[phys(base | (k << 5))] = R[k];
            __syncthreads();
        }

        // ============ Pass C: index bits 10..13 (wires 3..0) ============
        {
            #pragma unroll
            for (int k = 0; k < RPT; k++)
                R[k] = st[phys((k << 9) | tid)];
            #pragma unroll
            for (int p = 1; p < 5; p++)          // k bit p <-> i bit p+9
                APPLY(l * NQ + (4 - p), p);
            if (l < NL) {
                #pragma unroll
                for (int k = 0; k < RPT; k++)
                    st[phys((k << 9) | tid)] = R[k];
                __syncthreads();
            } else {
                // Fused expectation: sum |a_i|^2 * g(i), g(i) = sum_w +/- c_w.
                // i = (k<<9)|tid: tid bits 0..8 <-> wires 13..5, k bits 0..4 <-> wires 4..0
                float glow = 0.0f;
                #pragma unroll
                for (int bb = 0; bb < 9; bb++)
                    glow += ((tid >> bb) & 1) ? -csh[13 - bb] : csh[13 - bb];
                #pragma unroll
                for (int k = 0; k < RPT; k++) {
                    float gh = 0.0f;
                    #pragma unroll
                    for (int bb = 0; bb < 5; bb++)
                        gh += ((k >> bb) & 1) ? -csh[4 - bb] : csh[4 - bb];
                    local += (R[k].x * R[k].x + R[k].y * R[k].y) * (glow + gh);
                }
            }
        }
    }

    // deterministic reduction: warp shuffle, then serial over 16 warp sums
    #pragma unroll
    for (int off = 16; off; off >>= 1)
        local += __shfl_down_sync(0xffffffffu, local, off);
    if ((tid & 31) == 0) wsum[tid >> 5] = local;
    __syncthreads();
    if (tid == 0) {
        float tot = 0.0f;
        #pragma unroll
        for (int i = 0; i < THREADS / 32; i++) tot += wsum[i];
        // PLANAR complex output: out[0..B) = real (f1), out[B..2B) = imag (f2)
        out[circ * B + b] = tot;
    }
}

extern "C" void kernel_launch(void* const* d_in, const int* in_sizes, int n_in,
                              void* d_out, int out_size)
{
    // Input slot dispatch by element count:
    //   x = B*NQ (3584, unique large), q_* = 126 (x4), c_* = 14 (x2).
    const float *x, *qx1, *qz1, *c1, *qx2, *qz2, *c2;

    if (n_in >= 7 && in_sizes[0] > 1000) {
        // dict order: x, q_x1, q_z1, c1, q_x2, q_z2, c2
        x   = (const float*)d_in[0];
        qx1 = (const float*)d_in[1];
        qz1 = (const float*)d_in[2];
        c1  = (const float*)d_in[3];
        qx2 = (const float*)d_in[4];
        qz2 = (const float*)d_in[5];
        c2  = (const float*)d_in[6];
    } else if (n_in >= 7 && in_sizes[0] == NQ && in_sizes[1] == NQ) {
        // alphabetical: c1, c2, q_x1, q_x2, q_z1, q_z2, x
        c1  = (const float*)d_in[0];
        c2  = (const float*)d_in[1];
        qx1 = (const float*)d_in[2];
        qx2 = (const float*)d_in[3];
        qz1 = (const float*)d_in[4];
        qz2 = (const float*)d_in[5];
        x   = (const float*)d_in[6];
    } else {
        const float* qs[4] = {0, 0, 0, 0};
        const float* cs[2] = {0, 0};
        const float* xp = 0;
        int nq = 0, nc = 0;
        for (int i = 0; i < n_in; i++) {
            if (in_sizes[i] > 1000)         xp = (const float*)d_in[i];
            else if (in_sizes[i] == NGATES) { if (nq < 4) qs[nq++] = (const float*)d_in[i]; }
            else if (in_sizes[i] == NQ)     { if (nc < 2) cs[nc++] = (const float*)d_in[i]; }
        }
        x = xp; qx1 = qs[0]; qz1 = qs[1]; qx2 = qs[2]; qz2 = qs[3];
        c1 = cs[0]; c2 = cs[1];
    }

    int xsz = 0;
    for (int i = 0; i < n_in; i++) if (in_sizes[i] > xsz) xsz = in_sizes[i];
    const int B = xsz / NQ;  // 256

    cudaFuncSetAttribute(pqc_kernel,
                         cudaFuncAttributeMaxDynamicSharedMemorySize,
                         DIM * sizeof(float2));

    dim3 grid(B, 2);
    pqc_kernel<<<grid, THREADS, DIM * sizeof(float2)>>>(
        x, qx1, qz1, c1, qx2, qz2, c2, (float*)d_out, B);
}

// round 8
// speedup vs baseline: 1.9008x; 1.0093x over previous
#include <cuda_runtime.h>

#define NQ      14
#define DIM     (1 << NQ)       // 16384 amplitudes
#define HALF    (DIM / 2)       // 8192 packed u64 per plane
#define NL      8
#define NGATES  ((NL + 1) * NQ) // 126 single-qubit gates
#define THREADS 512

typedef unsigned long long u64;

// XOR swizzle on u64-plane index; all passes use the same mapping.
__device__ __forceinline__ int phys64(int p) { return p ^ ((p >> 4) & 15); }

__device__ __forceinline__ u64 pk2(float lo, float hi) {
    u64 r; asm("mov.b64 %0, {%1,%2};" : "=l"(r) : "f"(lo), "f"(hi)); return r;
}
__device__ __forceinline__ void upk2(u64 v, float& lo, float& hi) {
    asm("mov.b64 {%0,%1}, %2;" : "=f"(lo), "=f"(hi) : "l"(v));
}
__device__ __forceinline__ u64 swap2(u64 v) {
    float lo, hi; upk2(v, lo, hi); return pk2(hi, lo);
}
__device__ __forceinline__ u64 fma2(u64 a, u64 b, u64 c) {
    u64 d; asm("fma.rn.f32x2 %0, %1, %2, %3;" : "=l"(d) : "l"(a), "l"(b), "l"(c));
    return d;
}
__device__ __forceinline__ u64 mul2(u64 a, u64 b) {
    u64 d; asm("mul.rn.f32x2 %0, %1, %2;" : "=l"(d) : "l"(a), "l"(b));
    return d;
}

// Gate matrix structure (from U = [[pm*cx, pm*(-i sx)],[pp*(-i sx), pp*cx]]):
//   u00 = (a, b)   u01 = (c, d)
//   u10 = (-c, d)  u11 = (a, -b)
// with a=pr*cx, b=pii*cx, c=pii*sx, d=-pr*sx.

// Broadcast gate: butterfly partners are distinct packed elements (bit BIT of j).
template<int BIT>
__device__ __forceinline__ void gate_bcast(u64* PX, u64* PY, float4 g) {
    const float a = g.x, b = g.y, c = g.z, d = g.w;
    const u64 A  = pk2(a, a);
    const u64 Bp = pk2(b, b),  Bn = pk2(-b, -b);
    const u64 Cp = pk2(c, c),  Cn = pk2(-c, -c);
    const u64 Dp = pk2(d, d),  Dn = pk2(-d, -d);
    #pragma unroll
    for (int j = 0; j < 16; j++) {
        if (j & (1 << BIT)) continue;
        const int j2 = j | (1 << BIT);
        u64 x0 = PX[j], y0 = PY[j], x1 = PX[j2], y1 = PY[j2];
        // r0x = a*x0 - b*y0 + c*x1 - d*y1
        u64 r0x = fma2(A,  x0, fma2(Bn, y0, fma2(Cp, x1, mul2(Dn, y1))));
        // r0y = a*y0 + b*x0 + c*y1 + d*x1
        u64 r0y = fma2(A,  y0, fma2(Bp, x0, fma2(Cp, y1, mul2(Dp, x1))));
        // r1x = -c*x0 - d*y0 + a*x1 + b*y1
        u64 r1x = fma2(Cn, x0, fma2(Dn, y0, fma2(A,  x1, mul2(Bp, y1))));
        // r1y = -c*y0 + d*x0 + a*y1 - b*x1
        u64 r1y = fma2(Cn, y0, fma2(Dp, x0, fma2(A,  y1, mul2(Bn, x1))));
        PX[j] = r0x; PY[j] = r0y; PX[j2] = r1x; PY[j2] = r1y;
    }
}

// Pair-form gate: butterfly partners are the two lanes of each packed element.
__device__ __forceinline__ void gate_pair(u64* PX, u64* PY, float4 g) {
    const float a = g.x, b = g.y, c = g.z, d = g.w;
    const u64 A   = pk2(a, a);
    const u64 Or  = pk2(c, -c);
    const u64 Di  = pk2(b, -b), Din = pk2(-b, b);
    const u64 Oi  = pk2(d, d),  Oin = pk2(-d, -d);
    #pragma unroll
    for (int j = 0; j < 16; j++) {
        u64 px = PX[j], py = PY[j];
        u64 sx = swap2(px), sy = swap2(py);
        // lane0: a*x0 - b*y0 + c*x1 - d*y1 ; lane1: -c*x0 - d*y0 + a*x1 + b*y1
        u64 rx = fma2(A, px, fma2(Or, sx, fma2(Din, py, mul2(Oin, sy))));
        // lane0: a*y0 + b*x0 + c*y1 + d*x1 ; lane1: -c*y0 + d*x0 + a*y1 - b*x1
        u64 ry = fma2(A, py, fma2(Or, sy, fma2(Di,  px, mul2(Oi,  sx))));
        PX[j] = rx; PY[j] = ry;
    }
}

// One CTA simulates one (batch, circuit) pair. State lives in two swizzled
// u64 SMEM planes (packed x and y components). Each layer: 3 register passes.
__global__ void __launch_bounds__(THREADS, 1)
pqc_kernel(const float* __restrict__ x,
           const float* __restrict__ qx1, const float* __restrict__ qz1,
           const float* __restrict__ c1,
           const float* __restrict__ qx2, const float* __restrict__ qz2,
           const float* __restrict__ c2,
           float* __restrict__ out, int B)
{
    extern __shared__ u64 dsm[];            // 2 * HALF u64 = 128 KB
    u64* SX = dsm;
    u64* SY = dsm + HALF;
    __shared__ float4 U4[NGATES];           // gate coefficients (a,b,c,d)
    __shared__ float  csh[NQ];
    __shared__ float  amp[NQ][2];
    __shared__ float  wsum[THREADS / 32];

    const int tid  = threadIdx.x;
    const int b    = blockIdx.x;
    const int circ = blockIdx.y;

    const float* qx = circ ? qx2 : qx1;
    const float* qz = circ ? qz2 : qz1;
    const float* cc = circ ? c2  : c1;

    if (tid < NGATES) {
        float ax = 0.5f * qx[tid];
        float az = 0.5f * qz[tid];
        float cxv = cosf(ax), sxv = sinf(ax);
        float pr  = cosf(az), pii = -sinf(az);   // pm = (pr,pii), pp = conj
        U4[tid] = make_float4(pr * cxv, pii * cxv, pii * sxv, -pr * sxv);
    }
    if (tid < NQ) {
        csh[tid] = cc[tid];
        float bit = (x[b * NQ + tid] > 0.0f) ? 1.0f : 0.0f;
        float th = 1.5707963705062866f * bit;    // 0.5f * float32(pi) * bit
        amp[tid][0] = cosf(th);
        amp[tid][1] = sinf(th);
    }
    __syncthreads();

    u64 PX[16], PY[16];
    float local = 0.0f;

    for (int l = 0; l <= NL; l++) {
        const int gb = l * NQ;

        // ===== Pass A: owns i bits 0..4, pairing on bit 0 (wire 13) =====
        if (l == 0) {
            // init product state straight into packed registers
            float ph = 1.0f;
            #pragma unroll
            for (int w = 0; w < 9; w++)
                ph *= amp[w][(tid >> (8 - w)) & 1];
            const float a13_0 = amp[13][0], a13_1 = amp[13][1];
            #pragma unroll
            for (int j = 0; j < 16; j++) {
                float pj = ph;
                #pragma unroll
                for (int w = 9; w < 13; w++)
                    pj *= amp[w][(j >> (12 - w)) & 1];
                PX[j] = pk2(pj * a13_0, pj * a13_1);
                PY[j] = 0ULL;
            }
        } else {
            // fused CNOT-ladder (Gray) gather: dst 2m/2m+1 <- src (2m^m)^{0,1}
            #pragma unroll
            for (int j = 0; j < 16; j++) {
                int m  = (tid << 4) | j;
                int ps = m ^ (m >> 1);
                u64 vx = SX[phys64(ps)], vy = SY[phys64(ps)];
                if (j & 1) { vx = swap2(vx); vy = swap2(vy); }  // src pair lane-swapped
                PX[j] = vx; PY[j] = vy;
            }
        }
        gate_pair(PX, PY, U4[gb + 13]);
        gate_bcast<0>(PX, PY, U4[gb + 12]);
        gate_bcast<1>(PX, PY, U4[gb + 11]);
        gate_bcast<2>(PX, PY, U4[gb + 10]);
        gate_bcast<3>(PX, PY, U4[gb + 9]);
        if (l > 0) __syncthreads();         // all gathers read before overwrite
        #pragma unroll
        for (int j = 0; j < 16; j++) {
            int p = (tid << 4) | j;
            SX[phys64(p)] = PX[j]; SY[phys64(p)] = PY[j];
        }
        __syncthreads();

        // ===== Pass B: owns i bits 5..9, pairing on bit 5 (wire 8) =====
        {
            const int hi4 = tid >> 5, lo5 = tid & 31, lane = lo5 & 1;
            const float* fx = (const float*)SX;
            const float* fy = (const float*)SY;
            #pragma unroll
            for (int j = 0; j < 16; j++) {
                int p0 = (hi4 << 9) | (j << 5) | (lo5 >> 1);
                int p1 = p0 + 16;
                int a0 = 2 * phys64(p0) + lane, a1 = 2 * phys64(p1) + lane;
                PX[j] = pk2(fx[a0], fx[a1]);
                PY[j] = pk2(fy[a0], fy[a1]);
            }
            gate_pair(PX, PY, U4[gb + 8]);
            gate_bcast<0>(PX, PY, U4[gb + 7]);
            gate_bcast<1>(PX, PY, U4[gb + 6]);
            gate_bcast<2>(PX, PY, U4[gb + 5]);
            gate_bcast<3>(PX, PY, U4[gb + 4]);
            float* fxw = (float*)SX;
            float* fyw = (float*)SY;
            #pragma unroll
            for (int j = 0; j < 16; j++) {
                int p0 = (hi4 << 9) | (j << 5) | (lo5 >> 1);
                int p1 = p0 + 16;
                int a0 = 2 * phys64(p0) + lane, a1 = 2 * phys64(p1) + lane;
                float xl, xh, yl, yh;
                upk2(PX[j], xl, xh); upk2(PY[j], yl, yh);
                fxw[a0] = xl; fxw[a1] = xh; fyw[a0] = yl; fyw[a1] = yh;
            }
            __syncthreads();
        }

        // ===== Pass C: owns i bits {0,10..13}, pairing on bit 0 (ungated) =====
        {
            #pragma unroll
            for (int j = 0; j < 16; j++) {
                int p = (j << 9) | tid;
                PX[j] = SX[phys64(p)]; PY[j] = SY[phys64(p)];
            }
            gate_bcast<0>(PX, PY, U4[gb + 3]);
            gate_bcast<1>(PX, PY, U4[gb + 2]);
            gate_bcast<2>(PX, PY, U4[gb + 1]);
            gate_bcast<3>(PX, PY, U4[gb + 0]);
            if (l < NL) {
                #pragma unroll
                for (int j = 0; j < 16; j++) {
                    int p = (j << 9) | tid;
                    SX[phys64(p)] = PX[j]; SY[phys64(p)] = PY[j];
                }
                __syncthreads();
            } else {
                // Fused expectation. i = (j<<10) | (tid<<1) | lane.
                // wires 4..12 <-> tid bits (12-w); wire 13 <-> lane; wires 0..3 <-> j bits (3-w)
                float gt = 0.0f;
                #pragma unroll
                for (int w = 4; w < 13; w++)
                    gt += ((tid >> (12 - w)) & 1) ? -csh[w] : csh[w];
                const float c13 = csh[13];
                #pragma unroll
                for (int j = 0; j < 16; j++) {
                    float gj = 0.0f;
                    #pragma unroll
                    for (int w = 0; w < 4; w++)
                        gj += ((j >> (3 - w)) & 1) ? -csh[w] : csh[w];
                    float x0, x1, y0, y1;
                    upk2(PX[j], x0, x1); upk2(PY[j], y0, y1);
                    local += (x0 * x0 + y0 * y0) * (gt + gj + c13)
                           + (x1 * x1 + y1 * y1) * (gt + gj - c13);
                }
            }
        }
    }

    // deterministic reduction
    #pragma unroll
    for (int off = 16; off; off >>= 1)
        local += __shfl_down_sync(0xffffffffu, local, off);
    if ((tid & 31) == 0) wsum[tid >> 5] = local;
    __syncthreads();
    if (tid == 0) {
        float tot = 0.0f;
        #pragma unroll
        for (int i = 0; i < THREADS / 32; i++) tot += wsum[i];
        // PLANAR complex output: out[0..B) = real (f1), out[B..2B) = imag (f2)
        out[circ * B + b] = tot;
    }
}

extern "C" void kernel_launch(void* const* d_in, const int* in_sizes, int n_in,
                              void* d_out, int out_size)
{
    const float *x, *qx1, *qz1, *c1, *qx2, *qz2, *c2;

    if (n_in >= 7 && in_sizes[0] > 1000) {
        // dict order: x, q_x1, q_z1, c1, q_x2, q_z2, c2
        x   = (const float*)d_in[0];
        qx1 = (const float*)d_in[1];
        qz1 = (const float*)d_in[2];
        c1  = (const float*)d_in[3];
        qx2 = (const float*)d_in[4];
        qz2 = (const float*)d_in[5];
        c2  = (const float*)d_in[6];
    } else if (n_in >= 7 && in_sizes[0] == NQ && in_sizes[1] == NQ) {
        c1  = (const float*)d_in[0];
        c2  = (const float*)d_in[1];
        qx1 = (const float*)d_in[2];
        qx2 = (const float*)d_in[3];
        qz1 = (const float*)d_in[4];
        qz2 = (const float*)d_in[5];
        x   = (const float*)d_in[6];
    } else {
        const float* qs[4] = {0, 0, 0, 0};
        const float* cs[2] = {0, 0};
        const float* xp = 0;
        int nq = 0, nc = 0;
        for (int i = 0; i < n_in; i++) {
            if (in_sizes[i] > 1000)         xp = (const float*)d_in[i];
            else if (in_sizes[i] == NGATES) { if (nq < 4) qs[nq++] = (const float*)d_in[i]; }
            else if (in_sizes[i] == NQ)     { if (nc < 2) cs[nc++] = (const float*)d_in[i]; }
        }
        x = xp; qx1 = qs[0]; qz1 = qs[1]; qx2 = qs[2]; qz2 = qs[3];
        c1 = cs[0]; c2 = cs[1];
    }

    int xsz = 0;
    for (int i = 0; i < n_in; i++) if (in_sizes[i] > xsz) xsz = in_sizes[i];
    const int B = xsz / NQ;  // 256

    cudaFuncSetAttribute(pqc_kernel,
                         cudaFuncAttributeMaxDynamicSharedMemorySize,
                         DIM * sizeof(u64));   // 128 KB (2 planes of HALF u64)

    dim3 grid(B, 2);
    pqc_kernel<<<grid, THREADS, DIM * sizeof(u64)>>>(
        x, qx1, qz1, c1, qx2, qz2, c2, (float*)d_out, B);
}